// round 6
// baseline (speedup 1.0000x reference)
#include <cuda_runtime.h>
#include <cstdint>
#include <cstddef>

#define THREADS 256
#define NOUT 85

#define SA_STRIDE 136   // A tile [32 k][128 m] raw fp32, rows 128->136
#define SB_STRIDE 36    // B tile [96 n][32 k] tf32,     rows 32->36
#define SO_STRIDE 132   // epilogue [96 n][128 m]

#define SA_FLOATS (32 * SA_STRIDE)     // 4352
#define SB_FLOATS (96 * SB_STRIDE)     // 3456
// layout: A0 | A1 | B0 | B1
#define A0_OFF 0
#define A1_OFF SA_FLOATS
#define B0_OFF (2 * SA_FLOATS)
#define B1_OFF (2 * SA_FLOATS + SB_FLOATS)
#define DSMEM_BYTES ((2 * SA_FLOATS + 2 * SB_FLOATS) * 4)   // 62464

__device__ __forceinline__ uint32_t f2tf32(float x) {
    uint32_t r; asm("cvt.rna.tf32.f32 %0, %1;" : "=r"(r) : "f"(x)); return r;
}
__device__ __forceinline__ uint32_t cvt_raw(uint32_t raw) {
    uint32_t r; asm("cvt.rna.tf32.f32 %0, %1;" : "=r"(r) : "f"(__uint_as_float(raw))); return r;
}

__device__ __forceinline__ void mma_tf32(float c[4], const uint32_t a[4], const uint32_t b[2]) {
    asm volatile(
        "mma.sync.aligned.m16n8k8.row.col.f32.tf32.tf32.f32 "
        "{%0,%1,%2,%3}, {%4,%5,%6,%7}, {%8,%9}, {%0,%1,%2,%3};"
        : "+f"(c[0]), "+f"(c[1]), "+f"(c[2]), "+f"(c[3])
        : "r"(a[0]), "r"(a[1]), "r"(a[2]), "r"(a[3]), "r"(b[0]), "r"(b[1]));
}

__device__ __forceinline__ void cp_async16(uint32_t dst, const void* src) {
    asm volatile("cp.async.cg.shared.global [%0], [%1], 16;" :: "r"(dst), "l"(src));
}
__device__ __forceinline__ void cp_commit() { asm volatile("cp.async.commit_group;"); }
template <int N>
__device__ __forceinline__ void cp_wait() { asm volatile("cp.async.wait_group %0;" :: "n"(N)); }

__device__ __forceinline__ void ldsm_x4(uint32_t r[4], uint32_t addr) {
    asm volatile("ldmatrix.sync.aligned.m8n8.x4.shared.b16 {%0,%1,%2,%3}, [%4];"
                 : "=r"(r[0]), "=r"(r[1]), "=r"(r[2]), "=r"(r[3]) : "r"(addr));
}

// out[b, o, hw] = sum_c feat[b, c, hw] * W[o, c] + bias[o]
// GEMM: D[m, n], m = flat b*HW+hw (128-tile), n = o (85 -> 96), k = c.
__global__ __launch_bounds__(THREADS, 3)
void head_mma_kernel(const float* __restrict__ f0, const float* __restrict__ f1,
                     const float* __restrict__ f2,
                     const float* __restrict__ w0, const float* __restrict__ w1,
                     const float* __restrict__ w2,
                     const float* __restrict__ bi0, const float* __restrict__ bi1,
                     const float* __restrict__ bi2,
                     float* __restrict__ out)
{
    extern __shared__ float sm[];
    uint32_t* smu = reinterpret_cast<uint32_t*>(sm);
    const uint32_t smem_base = (uint32_t)__cvta_generic_to_shared(sm);

    const int tid  = threadIdx.x;
    const int wid  = tid >> 5;
    const int lane = tid & 31;

    // ---- level dispatch: heavy CTAs first ----
    const float* feat; const float* W; const float* bias; float* ob;
    int C, HW, nch, ntile;
    const int bid = blockIdx.x;
    if (bid < 50)       { feat = f2; W = w2; bias = bi2; ob = out + 10880000; C = 1024; HW = 400;  nch = 32; ntile = bid; }
    else if (bid < 250) { feat = f1; W = w1; bias = bi1; ob = out + 8704000;  C = 512;  HW = 1600; nch = 16; ntile = bid - 50; }
    else                { feat = f0; W = w0; bias = bi0; ob = out;            C = 256;  HW = 6400; nch = 8;  ntile = bid - 250; }

    const int m0 = ntile * 128;

    // ---- A cp.async mapping: 4 x 16B per thread per chunk ----
    // idx = tid + 256*i: k = idx>>5 (0..31), mq = idx&31
    const float* aSrc[4];     // advances by 32*HW per issued chunk
    uint32_t aDstB[4];        // byte offset within an A buffer
#pragma unroll
    for (int i = 0; i < 4; i++) {
        const int idx = tid + 256 * i;
        const int k = idx >> 5;
        const int mq = idx & 31;
        const int p = m0 + mq * 4;         // float4 never crosses batch (HW%4==0)
        const int b = p / HW;
        const int hw = p - b * HW;
        aSrc[i]  = feat + (size_t)b * C * HW + hw + (size_t)k * HW;
        aDstB[i] = (uint32_t)((k * SA_STRIDE + mq * 4) * 4);
    }

    // ---- B staging mapping: 3 float4 per thread per chunk ----
    const int bKq = tid & 7;
    const int bN0 = tid >> 3;

    // ---- warp tile: 4M x 2N; warp = 32m x 48n ----
    const int wm = wid & 3;
    const int wn = wid >> 2;
    const int g  = lane >> 2;
    const int tg = lane & 3;
    const int mA = wm * 32 + g;

    // ldmatrix per-lane address pieces (relative to B buffer base, bytes)
    // matrices: {n0..n0+7, k0..3}, {same, k4..7}, {n0+8.., k0..3}, {n0+8.., k4..7}
    const uint32_t bRow  = (uint32_t)(wn * 48 + ((lane >> 4) & 1) * 8 + (lane & 7));
    const uint32_t bByte = bRow * (SB_STRIDE * 4) + ((lane >> 3) & 1) * 16;

    float acc[2][6][4];
#pragma unroll
    for (int i = 0; i < 2; i++)
#pragma unroll
        for (int j = 0; j < 6; j++)
#pragma unroll
            for (int r = 0; r < 4; r++) acc[i][j][r] = 0.f;

    const int bufAOff[2] = { A0_OFF, A1_OFF };
    const int bufBOff[2] = { B0_OFF, B1_OFF };

    // ---------------- prologue ----------------
    // cp.async chunk 0 -> A0, chunk 1 -> A1
#pragma unroll
    for (int i = 0; i < 4; i++) cp_async16(smem_base + (uint32_t)(A0_OFF * 4) + aDstB[i], aSrc[i]);
    cp_commit();
#pragma unroll
    for (int i = 0; i < 4; i++) aSrc[i] += 32 * HW;
#pragma unroll
    for (int i = 0; i < 4; i++) cp_async16(smem_base + (uint32_t)(A1_OFF * 4) + aDstB[i], aSrc[i]);
    cp_commit();
#pragma unroll
    for (int i = 0; i < 4; i++) aSrc[i] += 32 * HW;

    // B chunk 0 -> B0
    float4 rb[3];
#pragma unroll
    for (int j = 0; j < 3; j++) {
        const int n = bN0 + 32 * j;
        rb[j] = (n < NOUT) ? *reinterpret_cast<const float4*>(W + (size_t)n * C + bKq * 4)
                           : make_float4(0.f, 0.f, 0.f, 0.f);
    }
#pragma unroll
    for (int j = 0; j < 3; j++) {
        uint4 w;
        w.x = f2tf32(rb[j].x); w.y = f2tf32(rb[j].y);
        w.z = f2tf32(rb[j].z); w.w = f2tf32(rb[j].w);
        const int n = bN0 + 32 * j;
        *reinterpret_cast<uint4*>(&smu[B0_OFF + n * SB_STRIDE + bKq * 4]) = w;
    }
    // B chunk 1 -> regs
#pragma unroll
    for (int j = 0; j < 3; j++) {
        const int n = bN0 + 32 * j;
        rb[j] = (n < NOUT) ? *reinterpret_cast<const float4*>(W + (size_t)n * C + 32 + bKq * 4)
                           : make_float4(0.f, 0.f, 0.f, 0.f);
    }

    cp_wait<1>();          // A(0) landed
    __syncthreads();

    // ---------------- main loop ----------------
    for (int t = 0; t < nch; t++) {
        const int cur = t & 1;
        const int nxt = cur ^ 1;

        // stage B(t+1) from regs; prefetch B(t+2) into regs
        if (t + 1 < nch) {
#pragma unroll
            for (int j = 0; j < 3; j++) {
                uint4 w;
                w.x = f2tf32(rb[j].x); w.y = f2tf32(rb[j].y);
                w.z = f2tf32(rb[j].z); w.w = f2tf32(rb[j].w);
                const int n = bN0 + 32 * j;
                *reinterpret_cast<uint4*>(&smu[bufBOff[nxt] + n * SB_STRIDE + bKq * 4]) = w;
            }
        }
        if (t + 2 < nch) {
            const int kc = (t + 2) * 32;
#pragma unroll
            for (int j = 0; j < 3; j++) {
                const int n = bN0 + 32 * j;
                rb[j] = (n < NOUT) ? *reinterpret_cast<const float4*>(W + (size_t)n * C + kc + bKq * 4)
                                   : make_float4(0.f, 0.f, 0.f, 0.f);
            }
        }

        // compute chunk t
        const uint32_t* sa = smu + bufAOff[cur];
        const uint32_t bBase = smem_base + (uint32_t)(bufBOff[cur] * 4);
#pragma unroll
        for (int ks = 0; ks < 4; ks++) {
            const int k0 = ks * 8 + tg;
            uint32_t afr[2][4];
#pragma unroll
            for (int i = 0; i < 2; i++) {
                const int mm = mA + 16 * i;
                afr[i][0] = cvt_raw(sa[k0 * SA_STRIDE + mm]);
                afr[i][1] = cvt_raw(sa[k0 * SA_STRIDE + mm + 8]);
                afr[i][2] = cvt_raw(sa[(k0 + 4) * SA_STRIDE + mm]);
                afr[i][3] = cvt_raw(sa[(k0 + 4) * SA_STRIDE + mm + 8]);
            }
            uint32_t bfr[6][2];
#pragma unroll
            for (int jp = 0; jp < 3; jp++) {
                uint32_t q[4];
                ldsm_x4(q, bBase + bByte + (uint32_t)(jp * 16 * SB_STRIDE * 4) + (uint32_t)(ks * 32));
                bfr[2 * jp][0] = q[0]; bfr[2 * jp][1] = q[1];
                bfr[2 * jp + 1][0] = q[2]; bfr[2 * jp + 1][1] = q[3];
            }
#pragma unroll
            for (int i = 0; i < 2; i++)
#pragma unroll
                for (int j = 0; j < 6; j++)
                    mma_tf32(acc[i][j], afr[i], bfr[j]);
        }

        __syncthreads();   // all warps done reading bufA[cur] / staging B(t+1)

        if (t + 2 < nch) {
            // refill bufA[cur] with chunk t+2 (async; lands during compute t+1)
#pragma unroll
            for (int i = 0; i < 4; i++)
                cp_async16(smem_base + (uint32_t)(bufAOff[cur] * 4) + aDstB[i], aSrc[i]);
            cp_commit();
#pragma unroll
            for (int i = 0; i < 4; i++) aSrc[i] += 32 * HW;
            cp_wait<1>();  // A(t+1) complete
        } else {
            cp_wait<0>();  // drain (A(t+1) if pending)
        }
        __syncthreads();
    }

    // ---- epilogue: transpose via smem, coalesced stores ----
    {
        const int mBase = wm * 32 + g;
        const int nBase = wn * 48 + tg * 2;
#pragma unroll
        for (int i = 0; i < 2; i++) {
#pragma unroll
            for (int j = 0; j < 6; j++) {
                const int n = nBase + 8 * j;
                const int m = mBase + 16 * i;
                sm[n * SO_STRIDE + m]           = acc[i][j][0];
                sm[(n + 1) * SO_STRIDE + m]     = acc[i][j][1];
                sm[n * SO_STRIDE + m + 8]       = acc[i][j][2];
                sm[(n + 1) * SO_STRIDE + m + 8] = acc[i][j][3];
            }
        }
    }
    __syncthreads();

#pragma unroll
    for (int j2 = 0; j2 < 12; j2++) {
        const int idx = j2 * 256 + tid;
        const int n = idx >> 5;
        const int mq = idx & 31;
        if (n < NOUT) {
            float4 v = *reinterpret_cast<const float4*>(&sm[n * SO_STRIDE + mq * 4]);
            const float bo = __ldg(&bias[n]);
            v.x += bo; v.y += bo; v.z += bo; v.w += bo;
            const int p = m0 + mq * 4;
            const int b = p / HW;
            const int hw = p - b * HW;
            *reinterpret_cast<float4*>(ob + ((size_t)b * NOUT + n) * HW + hw) = v;
        }
    }
}

extern "C" void kernel_launch(void* const* d_in, const int* in_sizes, int n_in,
                              void* d_out, int out_size)
{
    const float* feat[3] = {nullptr, nullptr, nullptr};
    const float* wgt[3]  = {nullptr, nullptr, nullptr};
    const float* bia[3]  = {nullptr, nullptr, nullptr};
    int bcount = 0;
    for (int i = 0; i < n_in; i++) {
        const int s = in_sizes[i];
        const float* p = (const float*)d_in[i];
        if      (s == 16 * 256 * 6400)  feat[0] = p;
        else if (s == 16 * 512 * 1600)  feat[1] = p;
        else if (s == 16 * 1024 * 400)  feat[2] = p;
        else if (s == 85 * 256)         wgt[0] = p;
        else if (s == 85 * 512)         wgt[1] = p;
        else if (s == 85 * 1024)        wgt[2] = p;
        else if (s == 85 && bcount < 3) bia[bcount++] = p;
    }

    cudaFuncSetAttribute(head_mma_kernel,
                         cudaFuncAttributeMaxDynamicSharedMemorySize, DSMEM_BYTES);

    head_mma_kernel<<<1050, THREADS, DSMEM_BYTES>>>(
        feat[0], feat[1], feat[2],
        wgt[0], wgt[1], wgt[2],
        bia[0], bia[1], bia[2],
        (float*)d_out);
}

// round 7
// speedup vs baseline: 1.5149x; 1.5149x over previous
#include <cuda_runtime.h>
#include <cstdint>
#include <cstddef>

#define THREADS 256
#define NOUT 85

#define SA_STRIDE 36    // A tile [128 m][32 k] tf32, rows padded 32->36 (144B, 16B-aligned)
#define SB_STRIDE 36    // B tile [96 n][32 k] tf32
#define SO_STRIDE 132   // epilogue [96 n][128 m]

#define SA_FLOATS (128 * SA_STRIDE)   // 4608
#define SB_FLOATS (96 * SB_STRIDE)    // 3456
#define A0_OFF 0
#define A1_OFF SA_FLOATS
#define B0_OFF (2 * SA_FLOATS)
#define B1_OFF (2 * SA_FLOATS + SB_FLOATS)
#define DSMEM_BYTES ((2 * SA_FLOATS + 2 * SB_FLOATS) * 4)   // 64512 >= epilogue 50688

__device__ __forceinline__ uint32_t f2tf32(float x) {
    uint32_t r; asm("cvt.rna.tf32.f32 %0, %1;" : "=r"(r) : "f"(x)); return r;
}

__device__ __forceinline__ void mma_tf32(float c[4], const uint32_t a[4], const uint32_t b[2]) {
    asm volatile(
        "mma.sync.aligned.m16n8k8.row.col.f32.tf32.tf32.f32 "
        "{%0,%1,%2,%3}, {%4,%5,%6,%7}, {%8,%9}, {%0,%1,%2,%3};"
        : "+f"(c[0]), "+f"(c[1]), "+f"(c[2]), "+f"(c[3])
        : "r"(a[0]), "r"(a[1]), "r"(a[2]), "r"(a[3]), "r"(b[0]), "r"(b[1]));
}

__device__ __forceinline__ void ldsm_x4(uint32_t r[4], uint32_t addr) {
    asm volatile("ldmatrix.sync.aligned.m8n8.x4.shared.b16 {%0,%1,%2,%3}, [%4];"
                 : "=r"(r[0]), "=r"(r[1]), "=r"(r[2]), "=r"(r[3]) : "r"(addr));
}

// out[b, o, hw] = sum_c feat[b, c, hw] * W[o, c] + bias[o]
// GEMM: D[m, n], m = flat b*HW+hw (128-tile), n = o (85 -> 96), k = c.
__global__ __launch_bounds__(THREADS, 2)
void head_mma_kernel(const float* __restrict__ f0, const float* __restrict__ f1,
                     const float* __restrict__ f2,
                     const float* __restrict__ w0, const float* __restrict__ w1,
                     const float* __restrict__ w2,
                     const float* __restrict__ bi0, const float* __restrict__ bi1,
                     const float* __restrict__ bi2,
                     float* __restrict__ out)
{
    extern __shared__ float sm[];
    uint32_t* smu = reinterpret_cast<uint32_t*>(sm);
    const uint32_t smem_base = (uint32_t)__cvta_generic_to_shared(sm);

    const int tid  = threadIdx.x;
    const int wid  = tid >> 5;
    const int lane = tid & 31;

    // ---- level dispatch: heavy CTAs first ----
    const float* feat; const float* W; const float* bias; float* ob;
    int C, HW, nch, ntile;
    const int bid = blockIdx.x;
    if (bid < 50)       { feat = f2; W = w2; bias = bi2; ob = out + 10880000; C = 1024; HW = 400;  nch = 32; ntile = bid; }
    else if (bid < 250) { feat = f1; W = w1; bias = bi1; ob = out + 8704000;  C = 512;  HW = 1600; nch = 16; ntile = bid - 50; }
    else                { feat = f0; W = w0; bias = bi0; ob = out;            C = 256;  HW = 6400; nch = 8;  ntile = bid - 250; }

    const int m0 = ntile * 128;

    // ---- A staging mapping: thread = (w = k-quad base 4w, mq = m-quad) ----
    const int w  = tid >> 5;        // k quad: thread loads k = 4w + i
    const int mq = tid & 31;        // m quad: m = mq*4 + r
    const int pA = m0 + mq * 4;     // flat position (float4 never crosses batch)
    const int bA = pA / HW;
    const size_t aOff = (size_t)bA * C * HW + (pA - bA * HW);
    // STS unit swizzle: store k-quad w of row m at 16B-unit (w + (m>>3)) & 7.
    // (m>>3) = (4mq+r)>>3 = mq>>1 for all r in 0..3.
    const int aUnit = (w + (mq >> 1)) & 7;
    int aDstF[4];   // float index within A buffer
#pragma unroll
    for (int r = 0; r < 4; r++)
        aDstF[r] = (mq * 4 + r) * SA_STRIDE + aUnit * 4;

    // ---- B staging mapping: 3 float4 per thread per chunk ----
    const int bKq = tid & 7;
    const int bN0 = tid >> 3;

    // ---- warp tile: 4M x 2N; warp = 32m x 48n ----
    const int wm = wid & 3;
    const int wn = wid >> 2;
    const int g  = lane >> 2;
    const int tg = lane & 3;
    (void)g; (void)tg;

    // A ldmatrix per-lane: rows, unit-half, swizzle shift
    const int aLaneRow = ((lane >> 3) & 1) * 8 + (lane & 7);     // 0..15
    const uint32_t aHi = (lane >> 4) & 1;                        // k-half within ks
    uint32_t aRowByte[2]; uint32_t aShift[2];
#pragma unroll
    for (int i = 0; i < 2; i++) {
        const int mloc = wm * 32 + i * 16 + aLaneRow;
        aRowByte[i] = (uint32_t)(mloc * SA_STRIDE * 4);
        aShift[i]   = (uint32_t)(mloc >> 3);
    }

    // B ldmatrix per-lane (R6-verified pattern)
    const uint32_t bRow  = (uint32_t)(wn * 48 + ((lane >> 4) & 1) * 8 + (lane & 7));
    const uint32_t bByte = bRow * (SB_STRIDE * 4) + ((lane >> 3) & 1) * 16;

    float acc[2][6][4];
#pragma unroll
    for (int i = 0; i < 2; i++)
#pragma unroll
        for (int j = 0; j < 6; j++)
#pragma unroll
            for (int r = 0; r < 4; r++) acc[i][j][r] = 0.f;

    const int bufAOff[2] = { A0_OFF, A1_OFF };
    const int bufBOff[2] = { B0_OFF, B1_OFF };

    float4 ra[4], rb[3];

    // ---- helpers as lambdas ----
    auto loadA = [&](int kc) {
#pragma unroll
        for (int i = 0; i < 4; i++)
            ra[i] = *reinterpret_cast<const float4*>(feat + aOff + (size_t)(kc + 4 * w + i) * HW);
    };
    auto loadB = [&](int kc) {
#pragma unroll
        for (int j = 0; j < 3; j++) {
            const int n = bN0 + 32 * j;
            rb[j] = (n < NOUT) ? *reinterpret_cast<const float4*>(W + (size_t)n * C + kc + bKq * 4)
                               : make_float4(0.f, 0.f, 0.f, 0.f);
        }
    };
    auto stage = [&](int buf) {
        // A: transpose 4k x 4m in registers -> 4 STS.128 along k
        const float va[4][4] = {
            { ra[0].x, ra[1].x, ra[2].x, ra[3].x },
            { ra[0].y, ra[1].y, ra[2].y, ra[3].y },
            { ra[0].z, ra[1].z, ra[2].z, ra[3].z },
            { ra[0].w, ra[1].w, ra[2].w, ra[3].w },
        };
#pragma unroll
        for (int r = 0; r < 4; r++) {
            uint4 u;
            u.x = f2tf32(va[r][0]); u.y = f2tf32(va[r][1]);
            u.z = f2tf32(va[r][2]); u.w = f2tf32(va[r][3]);
            *reinterpret_cast<uint4*>(&smu[bufAOff[buf] + aDstF[r]]) = u;
        }
#pragma unroll
        for (int j = 0; j < 3; j++) {
            uint4 u;
            u.x = f2tf32(rb[j].x); u.y = f2tf32(rb[j].y);
            u.z = f2tf32(rb[j].z); u.w = f2tf32(rb[j].w);
            const int n = bN0 + 32 * j;
            *reinterpret_cast<uint4*>(&smu[bufBOff[buf] + n * SB_STRIDE + bKq * 4]) = u;
        }
    };

    // ---------------- prologue ----------------
    loadA(0); loadB(0);
    stage(0);
    if (nch > 1) { loadA(32); loadB(32); }
    __syncthreads();

    // ---------------- main loop: 1 sync per chunk ----------------
    for (int t = 0; t < nch; t++) {
        const int cur = t & 1;
        const int nxt = cur ^ 1;

        if (t + 1 < nch) stage(nxt);
        if (t + 2 < nch) { loadA((t + 2) * 32); loadB((t + 2) * 32); }

        const uint32_t aBase = smem_base + (uint32_t)(bufAOff[cur] * 4);
        const uint32_t bBase = smem_base + (uint32_t)(bufBOff[cur] * 4);

#pragma unroll
        for (int ks = 0; ks < 4; ks++) {
            uint32_t afr[2][4];
#pragma unroll
            for (int i = 0; i < 2; i++) {
                const uint32_t unit = ((uint32_t)(2 * ks) + aHi + aShift[i]) & 7u;
                ldsm_x4(afr[i], aBase + aRowByte[i] + unit * 16u);
            }
            uint32_t bfr[6][2];
#pragma unroll
            for (int jp = 0; jp < 3; jp++) {
                uint32_t q[4];
                ldsm_x4(q, bBase + bByte + (uint32_t)(jp * 16 * SB_STRIDE * 4) + (uint32_t)(ks * 32));
                bfr[2 * jp][0] = q[0];     bfr[2 * jp][1] = q[1];
                bfr[2 * jp + 1][0] = q[2]; bfr[2 * jp + 1][1] = q[3];
            }
#pragma unroll
            for (int i = 0; i < 2; i++)
#pragma unroll
                for (int j = 0; j < 6; j++)
                    mma_tf32(acc[i][j], afr[i], bfr[j]);
        }

        __syncthreads();
    }

    // ---- epilogue: transpose via smem, coalesced stores ----
    {
        const int mBase = wm * 32 + g;
        const int nBase = wn * 48 + tg * 2;
#pragma unroll
        for (int i = 0; i < 2; i++) {
#pragma unroll
            for (int j = 0; j < 6; j++) {
                const int n = nBase + 8 * j;
                const int m = mBase + 16 * i;
                sm[n * SO_STRIDE + m]           = acc[i][j][0];
                sm[(n + 1) * SO_STRIDE + m]     = acc[i][j][1];
                sm[n * SO_STRIDE + m + 8]       = acc[i][j][2];
                sm[(n + 1) * SO_STRIDE + m + 8] = acc[i][j][3];
            }
        }
    }
    __syncthreads();

#pragma unroll
    for (int j2 = 0; j2 < 12; j2++) {
        const int idx = j2 * 256 + tid;
        const int n = idx >> 5;
        const int mqe = idx & 31;
        if (n < NOUT) {
            float4 v = *reinterpret_cast<const float4*>(&sm[n * SO_STRIDE + mqe * 4]);
            const float bo = __ldg(&bias[n]);
            v.x += bo; v.y += bo; v.z += bo; v.w += bo;
            const int p = m0 + mqe * 4;
            const int b = p / HW;
            const int hw = p - b * HW;
            *reinterpret_cast<float4*>(ob + ((size_t)b * NOUT + n) * HW + hw) = v;
        }
    }
}

extern "C" void kernel_launch(void* const* d_in, const int* in_sizes, int n_in,
                              void* d_out, int out_size)
{
    const float* feat[3] = {nullptr, nullptr, nullptr};
    const float* wgt[3]  = {nullptr, nullptr, nullptr};
    const float* bia[3]  = {nullptr, nullptr, nullptr};
    int bcount = 0;
    for (int i = 0; i < n_in; i++) {
        const int s = in_sizes[i];
        const float* p = (const float*)d_in[i];
        if      (s == 16 * 256 * 6400)  feat[0] = p;
        else if (s == 16 * 512 * 1600)  feat[1] = p;
        else if (s == 16 * 1024 * 400)  feat[2] = p;
        else if (s == 85 * 256)         wgt[0] = p;
        else if (s == 85 * 512)         wgt[1] = p;
        else if (s == 85 * 1024)        wgt[2] = p;
        else if (s == 85 && bcount < 3) bia[bcount++] = p;
    }

    cudaFuncSetAttribute(head_mma_kernel,
                         cudaFuncAttributeMaxDynamicSharedMemorySize, DSMEM_BYTES);

    head_mma_kernel<<<1050, THREADS, DSMEM_BYTES>>>(
        feat[0], feat[1], feat[2],
        wgt[0], wgt[1], wgt[2],
        bia[0], bia[1], bia[2],
        (float*)d_out);
}